// round 1
// baseline (speedup 1.0000x reference)
#include <cuda_runtime.h>
#include <cuda_bf16.h>

#define S_TOK     2304
#define D_MODEL   3072
#define NHEAD     24
#define HDIM      128
#define BLOCK_TOK 2048
#define CONDN     256
#define RANKN     128
#define T_IPN     128
#define D_IPN     4096
#define EPSV      1e-5f

// ---------------- device scratch (no allocations allowed) ----------------
__device__ float g_q[S_TOK * D_MODEL];
__device__ float g_k[S_TOK * D_MODEL];
__device__ float g_v[S_TOK * D_MODEL];
__device__ float g_kip[T_IPN * D_MODEL];
__device__ float g_vip[T_IPN * D_MODEL];
__device__ float g_lt[3 * CONDN * RANKN];

// ---------------- GEMM: C[M,N] (+)= A[M,K] @ B[N,K]^T + bias ----------------
// 128x128 tile, BK=16, 256 threads, 8x8 per thread. Grid = (N/128, M/128).
template <bool ACC>
__global__ __launch_bounds__(256) void gemm_nt(
    const float* __restrict__ A, const float* __restrict__ B,
    const float* __restrict__ bias, float* __restrict__ C,
    int K, int lda, int ldb, int ldc)
{
    __shared__ float As[16][132];
    __shared__ float Bs[16][132];
    const int tid = threadIdx.x;
    const int ty = tid >> 4, tx = tid & 15;
    const int bm = blockIdx.y << 7;
    const int bn = blockIdx.x << 7;
    const int lr = tid >> 2;            // 0..63
    const int lk = (tid & 3) << 2;      // 0,4,8,12

    const float* Ag = A + (size_t)(bm + lr) * lda + lk;
    const float* Bg = B + (size_t)(bn + lr) * ldb + lk;

    float acc[8][8];
#pragma unroll
    for (int i = 0; i < 8; i++)
#pragma unroll
        for (int j = 0; j < 8; j++) acc[i][j] = 0.f;

    for (int k0 = 0; k0 < K; k0 += 16) {
        float4 a0 = *(const float4*)(Ag + k0);
        float4 a1 = *(const float4*)(Ag + (size_t)64 * lda + k0);
        float4 b0 = *(const float4*)(Bg + k0);
        float4 b1 = *(const float4*)(Bg + (size_t)64 * ldb + k0);
        __syncthreads();
        As[lk + 0][lr] = a0.x; As[lk + 1][lr] = a0.y; As[lk + 2][lr] = a0.z; As[lk + 3][lr] = a0.w;
        As[lk + 0][lr + 64] = a1.x; As[lk + 1][lr + 64] = a1.y; As[lk + 2][lr + 64] = a1.z; As[lk + 3][lr + 64] = a1.w;
        Bs[lk + 0][lr] = b0.x; Bs[lk + 1][lr] = b0.y; Bs[lk + 2][lr] = b0.z; Bs[lk + 3][lr] = b0.w;
        Bs[lk + 0][lr + 64] = b1.x; Bs[lk + 1][lr + 64] = b1.y; Bs[lk + 2][lr + 64] = b1.z; Bs[lk + 3][lr + 64] = b1.w;
        __syncthreads();
#pragma unroll
        for (int kk = 0; kk < 16; kk++) {
            float4 aA = *(const float4*)&As[kk][ty << 2];
            float4 aB = *(const float4*)&As[kk][64 + (ty << 2)];
            float4 bA = *(const float4*)&Bs[kk][tx << 2];
            float4 bB = *(const float4*)&Bs[kk][64 + (tx << 2)];
            float av[8] = {aA.x, aA.y, aA.z, aA.w, aB.x, aB.y, aB.z, aB.w};
            float bv[8] = {bA.x, bA.y, bA.z, bA.w, bB.x, bB.y, bB.z, bB.w};
#pragma unroll
            for (int i = 0; i < 8; i++)
#pragma unroll
                for (int j = 0; j < 8; j++) acc[i][j] += av[i] * bv[j];
        }
    }

#pragma unroll
    for (int ih = 0; ih < 2; ih++)
#pragma unroll
        for (int i = 0; i < 4; i++) {
            int r = bm + ih * 64 + (ty << 2) + i;
#pragma unroll
            for (int jh = 0; jh < 2; jh++) {
                int c = bn + jh * 64 + (tx << 2);
                float4 val;
                val.x = acc[ih * 4 + i][jh * 4 + 0];
                val.y = acc[ih * 4 + i][jh * 4 + 1];
                val.z = acc[ih * 4 + i][jh * 4 + 2];
                val.w = acc[ih * 4 + i][jh * 4 + 3];
                float* cp = C + (size_t)r * ldc + c;
                if (bias) {
                    float4 bb = *(const float4*)(bias + c);
                    val.x += bb.x; val.y += bb.y; val.z += bb.z; val.w += bb.w;
                }
                if (ACC) {
                    float4 o = *(const float4*)cp;
                    val.x += o.x; val.y += o.y; val.z += o.z; val.w += o.w;
                }
                *(float4*)cp = val;
            }
        }
}

// ---------------- rmsnorm (+weight) (+rope), one warp per (token, head) ----------------
__global__ void norm_rope_kernel(float* __restrict__ t, const float* __restrict__ w,
                                 const float* __restrict__ cs, const float* __restrict__ sn,
                                 int rows, int do_rope)
{
    int gwarp = (blockIdx.x * blockDim.x + threadIdx.x) >> 5;
    int lane = threadIdx.x & 31;
    if (gwarp >= rows * NHEAD) return;
    int s = gwarp / NHEAD, h = gwarp % NHEAD;
    float* p = t + (size_t)s * D_MODEL + h * HDIM + lane * 4;
    float4 x = *(const float4*)p;
    float ss = x.x * x.x + x.y * x.y + x.z * x.z + x.w * x.w;
#pragma unroll
    for (int off = 16; off >= 1; off >>= 1) ss += __shfl_xor_sync(0xffffffffu, ss, off);
    float inv = rsqrtf(ss * (1.0f / HDIM) + EPSV);
    x.x *= inv; x.y *= inv; x.z *= inv; x.w *= inv;
    if (w) {
        float4 wv = *(const float4*)(w + lane * 4);
        x.x *= wv.x; x.y *= wv.y; x.z *= wv.z; x.w *= wv.w;
    }
    if (do_rope) {
        float4 c = *(const float4*)(cs + (size_t)s * HDIM + lane * 4);
        float4 v = *(const float4*)(sn + (size_t)s * HDIM + lane * 4);
        float o0 = x.x * c.x - x.y * v.x;
        float o1 = x.y * c.y + x.x * v.y;
        float o2 = x.z * c.z - x.w * v.z;
        float o3 = x.w * c.w + x.z * v.w;
        x.x = o0; x.y = o1; x.z = o2; x.w = o3;
    }
    *(float4*)p = x;
}

// ---------------- flash attention: 64 q-rows x 64-key tiles, 256 threads ----------------
// masked=1: q rows >= BLOCK_TOK only see keys [BLOCK_TOK, kv_len); else full range.
// addout=1: accumulate into Out (softmax-normalized independently).
__global__ __launch_bounds__(256) void attn_kernel(
    const float* __restrict__ Q, const float* __restrict__ Kp,
    const float* __restrict__ Vp, float* __restrict__ Out,
    int kv_len, int ldkv, int masked, int addout)
{
    extern __shared__ float smf[];
    float* Qs = smf;                  // [64][132]
    float* Ks = smf + 64 * 132;       // [64][132]
    float* Vs = smf + 2 * 64 * 132;   // [64][132]
    float* Ps = smf + 3 * 64 * 132;   // [64][68]

    const int tid = threadIdx.x;
    const int ty = tid >> 4, tx = tid & 15;
    const int h = blockIdx.y;
    const int q0 = blockIdx.x << 6;
    const float scale = 0.08838834764831845f;  // 1/sqrt(128)

#pragma unroll
    for (int t = 0; t < 8; t++) {
        int idx = tid + (t << 8);
        int r = idx >> 5;
        int f = (idx & 31) << 2;
        float4 v = *(const float4*)(Q + (size_t)(q0 + r) * D_MODEL + h * HDIM + f);
        v.x *= scale; v.y *= scale; v.z *= scale; v.w *= scale;
        *(float4*)&Qs[r * 132 + f] = v;
    }

    float m_i[4], l_i[4], o[4][8];
#pragma unroll
    for (int i = 0; i < 4; i++) {
        m_i[i] = -1e30f; l_i[i] = 0.f;
#pragma unroll
        for (int c = 0; c < 8; c++) o[i][c] = 0.f;
    }

    int kt0 = (masked && q0 >= BLOCK_TOK) ? BLOCK_TOK : 0;
    for (int kt = kt0; kt < kv_len; kt += 64) {
        __syncthreads();
#pragma unroll
        for (int t = 0; t < 8; t++) {
            int idx = tid + (t << 8);
            int r = idx >> 5;
            int f = (idx & 31) << 2;
            *(float4*)&Ks[r * 132 + f] = *(const float4*)(Kp + (size_t)(kt + r) * ldkv + h * HDIM + f);
            *(float4*)&Vs[r * 132 + f] = *(const float4*)(Vp + (size_t)(kt + r) * ldkv + h * HDIM + f);
        }
        __syncthreads();

        float s[4][4];
#pragma unroll
        for (int i = 0; i < 4; i++)
#pragma unroll
            for (int j = 0; j < 4; j++) s[i][j] = 0.f;

        for (int d = 0; d < HDIM; d += 4) {
            float4 q4[4], k4[4];
#pragma unroll
            for (int i = 0; i < 4; i++) q4[i] = *(const float4*)&Qs[((ty << 2) + i) * 132 + d];
#pragma unroll
            for (int j = 0; j < 4; j++) k4[j] = *(const float4*)&Ks[((tx << 2) + j) * 132 + d];
#pragma unroll
            for (int i = 0; i < 4; i++)
#pragma unroll
                for (int j = 0; j < 4; j++)
                    s[i][j] += q4[i].x * k4[j].x + q4[i].y * k4[j].y +
                               q4[i].z * k4[j].z + q4[i].w * k4[j].w;
        }

#pragma unroll
        for (int i = 0; i < 4; i++) {
            float rm = fmaxf(fmaxf(s[i][0], s[i][1]), fmaxf(s[i][2], s[i][3]));
#pragma unroll
            for (int off = 8; off >= 1; off >>= 1) rm = fmaxf(rm, __shfl_xor_sync(0xffffffffu, rm, off));
            float mn = fmaxf(m_i[i], rm);
            float al = __expf(m_i[i] - mn);
            m_i[i] = mn;
            float rs = 0.f;
#pragma unroll
            for (int j = 0; j < 4; j++) { s[i][j] = __expf(s[i][j] - mn); rs += s[i][j]; }
#pragma unroll
            for (int off = 8; off >= 1; off >>= 1) rs += __shfl_xor_sync(0xffffffffu, rs, off);
            l_i[i] = l_i[i] * al + rs;
#pragma unroll
            for (int c = 0; c < 8; c++) o[i][c] *= al;
            float4 pv = make_float4(s[i][0], s[i][1], s[i][2], s[i][3]);
            *(float4*)&Ps[((ty << 2) + i) * 68 + (tx << 2)] = pv;
        }
        __syncthreads();

        for (int j = 0; j < 64; j += 4) {
            float4 p4[4];
#pragma unroll
            for (int i = 0; i < 4; i++) p4[i] = *(const float4*)&Ps[((ty << 2) + i) * 68 + j];
#pragma unroll
            for (int jj = 0; jj < 4; jj++) {
                float4 va = *(const float4*)&Vs[(j + jj) * 132 + (tx << 2)];
                float4 vb = *(const float4*)&Vs[(j + jj) * 132 + 64 + (tx << 2)];
#pragma unroll
                for (int i = 0; i < 4; i++) {
                    float p = (jj == 0) ? p4[i].x : (jj == 1) ? p4[i].y : (jj == 2) ? p4[i].z : p4[i].w;
                    o[i][0] += p * va.x; o[i][1] += p * va.y; o[i][2] += p * va.z; o[i][3] += p * va.w;
                    o[i][4] += p * vb.x; o[i][5] += p * vb.y; o[i][6] += p * vb.z; o[i][7] += p * vb.w;
                }
            }
        }
    }

#pragma unroll
    for (int i = 0; i < 4; i++) {
        int r = q0 + (ty << 2) + i;
        float inv = 1.f / l_i[i];
        float* op = Out + (size_t)r * D_MODEL + h * HDIM;
        float4 va = make_float4(o[i][0] * inv, o[i][1] * inv, o[i][2] * inv, o[i][3] * inv);
        float4 vb = make_float4(o[i][4] * inv, o[i][5] * inv, o[i][6] * inv, o[i][7] * inv);
        if (addout) {
            float4 e0 = *(const float4*)(op + (tx << 2));
            float4 e1 = *(const float4*)(op + 64 + (tx << 2));
            va.x += e0.x; va.y += e0.y; va.z += e0.z; va.w += e0.w;
            vb.x += e1.x; vb.y += e1.y; vb.z += e1.z; vb.w += e1.w;
        }
        *(float4*)(op + (tx << 2)) = va;
        *(float4*)(op + 64 + (tx << 2)) = vb;
    }
}

// ---------------- host launcher ----------------
extern "C" void kernel_launch(void* const* d_in, const int* in_sizes, int n_in,
                              void* d_out, int out_size)
{
    (void)in_sizes; (void)n_in; (void)out_size;
    const float* x    = (const float*)d_in[0];
    const float* img  = (const float*)d_in[1];
    const float* cosr = (const float*)d_in[2];
    const float* sinr = (const float*)d_in[3];
    const float* Wq   = (const float*)d_in[4];
    const float* bq   = (const float*)d_in[5];
    const float* Wk   = (const float*)d_in[6];
    const float* bk   = (const float*)d_in[7];
    const float* Wv   = (const float*)d_in[8];
    const float* bv   = (const float*)d_in[9];
    const float* qd   = (const float*)d_in[10];
    const float* qu   = (const float*)d_in[11];
    const float* kd   = (const float*)d_in[12];
    const float* ku   = (const float*)d_in[13];
    const float* vd   = (const float*)d_in[14];
    const float* vu   = (const float*)d_in[15];
    const float* nqw  = (const float*)d_in[16];
    const float* nkw  = (const float*)d_in[17];
    const float* Wkip = (const float*)d_in[18];
    const float* Wvip = (const float*)d_in[19];
    float* out = (float*)d_out;

    float *q, *k, *v, *kip, *vip, *lt;
    cudaGetSymbolAddress((void**)&q,   g_q);
    cudaGetSymbolAddress((void**)&k,   g_k);
    cudaGetSymbolAddress((void**)&v,   g_v);
    cudaGetSymbolAddress((void**)&kip, g_kip);
    cudaGetSymbolAddress((void**)&vip, g_vip);
    cudaGetSymbolAddress((void**)&lt,  g_lt);

    dim3 blk(256);

    // QKV projections: [2304 x 3072 x 3072]
    gemm_nt<false><<<dim3(D_MODEL / 128, S_TOK / 128), blk>>>(x, Wq, bq, q, D_MODEL, D_MODEL, D_MODEL, D_MODEL);
    gemm_nt<false><<<dim3(D_MODEL / 128, S_TOK / 128), blk>>>(x, Wk, bk, k, D_MODEL, D_MODEL, D_MODEL, D_MODEL);
    gemm_nt<false><<<dim3(D_MODEL / 128, S_TOK / 128), blk>>>(x, Wv, bv, v, D_MODEL, D_MODEL, D_MODEL, D_MODEL);

    // LoRA down: [256 x 128 x 3072] on cond rows only
    const float* xc = x + (size_t)BLOCK_TOK * D_MODEL;
    gemm_nt<false><<<dim3(1, 2), blk>>>(xc, qd, nullptr, lt,                   D_MODEL, D_MODEL, D_MODEL, RANKN);
    gemm_nt<false><<<dim3(1, 2), blk>>>(xc, kd, nullptr, lt + CONDN * RANKN,     D_MODEL, D_MODEL, D_MODEL, RANKN);
    gemm_nt<false><<<dim3(1, 2), blk>>>(xc, vd, nullptr, lt + 2 * CONDN * RANKN, D_MODEL, D_MODEL, D_MODEL, RANKN);
    // LoRA up (accumulate into q/k/v rows 2048..): [256 x 3072 x 128], alpha/rank * lora_w = 1
    gemm_nt<true><<<dim3(D_MODEL / 128, 2), blk>>>(lt,                   qu, nullptr, q + (size_t)BLOCK_TOK * D_MODEL, RANKN, RANKN, RANKN, D_MODEL);
    gemm_nt<true><<<dim3(D_MODEL / 128, 2), blk>>>(lt + CONDN * RANKN,     ku, nullptr, k + (size_t)BLOCK_TOK * D_MODEL, RANKN, RANKN, RANKN, D_MODEL);
    gemm_nt<true><<<dim3(D_MODEL / 128, 2), blk>>>(lt + 2 * CONDN * RANKN, vu, nullptr, v + (size_t)BLOCK_TOK * D_MODEL, RANKN, RANKN, RANKN, D_MODEL);

    // RMSNorm + RoPE on q, k
    int nw = S_TOK * NHEAD;
    norm_rope_kernel<<<(nw * 32 + 255) / 256, 256>>>(q, nqw, cosr, sinr, S_TOK, 1);
    norm_rope_kernel<<<(nw * 32 + 255) / 256, 256>>>(k, nkw, cosr, sinr, S_TOK, 1);

    // IP projections: [128 x 3072 x 4096]
    gemm_nt<false><<<dim3(D_MODEL / 128, 1), blk>>>(img, Wkip, nullptr, kip, D_IPN, D_IPN, D_IPN, D_MODEL);
    gemm_nt<false><<<dim3(D_MODEL / 128, 1), blk>>>(img, Wvip, nullptr, vip, D_IPN, D_IPN, D_IPN, D_MODEL);
    // RMSNorm (no weight, no rope) on k_ip
    int nwip = T_IPN * NHEAD;
    norm_rope_kernel<<<(nwip * 32 + 255) / 256, 256>>>(kip, nullptr, nullptr, nullptr, T_IPN, 0);

    // Attention
    size_t smem = (size_t)(3 * 64 * 132 + 64 * 68) * sizeof(float);  // 116 KB
    cudaFuncSetAttribute(attn_kernel, cudaFuncAttributeMaxDynamicSharedMemorySize, (int)smem);
    // main attention: block-masked, overwrite out
    attn_kernel<<<dim3(S_TOK / 64, NHEAD), blk, smem>>>(q, k, v, out, S_TOK, D_MODEL, 1, 0);
    // IP attention: 128 keys, no mask, accumulate into out
    attn_kernel<<<dim3(S_TOK / 64, NHEAD), blk, smem>>>(q, kip, vip, out, T_IPN, D_MODEL, 0, 1);
}

// round 2
// speedup vs baseline: 2.7741x; 2.7741x over previous
#include <cuda_runtime.h>

#define S_TOK     2304
#define D_MODEL   3072
#define NHEAD     24
#define HDIM      128
#define BLOCK_TOK 2048
#define CONDN     256
#define RANKN     128
#define T_IPN     128
#define D_IPN     4096
#define EPSV      1e-5f
// (1/sqrt(128)) * log2(e), so softmax exp -> exp2
#define QSCALE    0.1275173e+0f

// ---------------- device scratch ----------------
__device__ float g_q[S_TOK * D_MODEL];
__device__ float g_k[S_TOK * D_MODEL];
__device__ float g_v[S_TOK * D_MODEL];
__device__ float g_kip[T_IPN * D_MODEL];
__device__ float g_vip[T_IPN * D_MODEL];
__device__ float g_lt[3 * CONDN * RANKN];

// ---------------- helpers ----------------
__device__ __forceinline__ unsigned f2tf(float f) {
    unsigned u;
    asm("cvt.rna.tf32.f32 %0, %1;" : "=r"(u) : "f"(f));
    return u;
}

__device__ __forceinline__ void mma8(float* c, const unsigned* a, unsigned b0, unsigned b1) {
    asm volatile(
        "mma.sync.aligned.m16n8k8.row.col.f32.tf32.tf32.f32 "
        "{%0,%1,%2,%3}, {%4,%5,%6,%7}, {%8,%9}, {%0,%1,%2,%3};"
        : "+f"(c[0]), "+f"(c[1]), "+f"(c[2]), "+f"(c[3])
        : "r"(a[0]), "r"(a[1]), "r"(a[2]), "r"(a[3]), "r"(b0), "r"(b1));
}

// ================= GEMM (tf32 tensor): C[M,N] (+)= A[M,K] @ B[N,K]^T + bias =================
// 128x128 block tile, BK=16, 128 threads (4 warps), warp tile 64x64.
// Smem k-major [k][mn] stride 136 -> conflict-free frag LDS and transpose STS.
struct Gemm3 {
    const float* A[3];
    const float* B[3];
    const float* bias[3];
    float*       C[3];
};

template <bool ACC>
__global__ __launch_bounds__(128, 2) void gemm_tc(Gemm3 P, int K, int lda, int ldb, int ldc)
{
    __shared__ unsigned As[2][16 * 136];
    __shared__ unsigned Bs[2][16 * 136];

    const int z = blockIdx.z;
    const float* A    = P.A[z];
    const float* B    = P.B[z];
    const float* bias = P.bias[z];
    float*       C    = P.C[z];

    const int tid = threadIdx.x;
    const int l = tid & 31, w = tid >> 5;
    const int g = l >> 2, t = l & 3;
    const int wm = w & 1, wn = w >> 1;
    const int bm = blockIdx.y << 7, bn = blockIdx.x << 7;

    const float* Ar = A + (size_t)(bm + tid) * lda;
    const float* Br = B + (size_t)(bn + tid) * ldb;

    float c[4][8][4];
#pragma unroll
    for (int mt = 0; mt < 4; mt++)
#pragma unroll
        for (int nt = 0; nt < 8; nt++)
#pragma unroll
            for (int i = 0; i < 4; i++) c[mt][nt][i] = 0.f;

    float4 a4[4], b4[4];
#pragma unroll
    for (int i = 0; i < 4; i++) {
        a4[i] = *(const float4*)(Ar + i * 4);
        b4[i] = *(const float4*)(Br + i * 4);
    }
#pragma unroll
    for (int i = 0; i < 4; i++) {
        As[0][(i * 4 + 0) * 136 + tid] = f2tf(a4[i].x);
        As[0][(i * 4 + 1) * 136 + tid] = f2tf(a4[i].y);
        As[0][(i * 4 + 2) * 136 + tid] = f2tf(a4[i].z);
        As[0][(i * 4 + 3) * 136 + tid] = f2tf(a4[i].w);
        Bs[0][(i * 4 + 0) * 136 + tid] = f2tf(b4[i].x);
        Bs[0][(i * 4 + 1) * 136 + tid] = f2tf(b4[i].y);
        Bs[0][(i * 4 + 2) * 136 + tid] = f2tf(b4[i].z);
        Bs[0][(i * 4 + 3) * 136 + tid] = f2tf(b4[i].w);
    }
    __syncthreads();

    const int niter = K >> 4;
    for (int it = 0; it < niter; it++) {
        const int cur = it & 1;
        if (it + 1 < niter) {
            const int k0 = (it + 1) << 4;
#pragma unroll
            for (int i = 0; i < 4; i++) {
                a4[i] = *(const float4*)(Ar + k0 + i * 4);
                b4[i] = *(const float4*)(Br + k0 + i * 4);
            }
        }
#pragma unroll
        for (int ks = 0; ks < 2; ks++) {
            const int kr = ks * 8 + t;
            unsigned af[4][4], bf[8][2];
#pragma unroll
            for (int mt = 0; mt < 4; mt++) {
                const int m0 = wm * 64 + mt * 16;
                af[mt][0] = As[cur][kr * 136 + m0 + g];
                af[mt][1] = As[cur][kr * 136 + m0 + g + 8];
                af[mt][2] = As[cur][(kr + 4) * 136 + m0 + g];
                af[mt][3] = As[cur][(kr + 4) * 136 + m0 + g + 8];
            }
#pragma unroll
            for (int nt = 0; nt < 8; nt++) {
                const int n0 = wn * 64 + nt * 8;
                bf[nt][0] = Bs[cur][kr * 136 + n0 + g];
                bf[nt][1] = Bs[cur][(kr + 4) * 136 + n0 + g];
            }
#pragma unroll
            for (int mt = 0; mt < 4; mt++)
#pragma unroll
                for (int nt = 0; nt < 8; nt++)
                    mma8(c[mt][nt], af[mt], bf[nt][0], bf[nt][1]);
        }
        __syncthreads();
        if (it + 1 < niter) {
            const int nxt = cur ^ 1;
#pragma unroll
            for (int i = 0; i < 4; i++) {
                As[nxt][(i * 4 + 0) * 136 + tid] = f2tf(a4[i].x);
                As[nxt][(i * 4 + 1) * 136 + tid] = f2tf(a4[i].y);
                As[nxt][(i * 4 + 2) * 136 + tid] = f2tf(a4[i].z);
                As[nxt][(i * 4 + 3) * 136 + tid] = f2tf(a4[i].w);
                Bs[nxt][(i * 4 + 0) * 136 + tid] = f2tf(b4[i].x);
                Bs[nxt][(i * 4 + 1) * 136 + tid] = f2tf(b4[i].y);
                Bs[nxt][(i * 4 + 2) * 136 + tid] = f2tf(b4[i].z);
                Bs[nxt][(i * 4 + 3) * 136 + tid] = f2tf(b4[i].w);
            }
        }
        __syncthreads();
    }

    // epilogue
#pragma unroll
    for (int mt = 0; mt < 4; mt++) {
        const int r0 = bm + wm * 64 + mt * 16 + g;
        const int r1 = r0 + 8;
#pragma unroll
        for (int nt = 0; nt < 8; nt++) {
            const int cc = bn + wn * 64 + nt * 8 + 2 * t;
            float2 v0 = make_float2(c[mt][nt][0], c[mt][nt][1]);
            float2 v1 = make_float2(c[mt][nt][2], c[mt][nt][3]);
            if (bias) {
                float bx = bias[cc], by = bias[cc + 1];
                v0.x += bx; v0.y += by; v1.x += bx; v1.y += by;
            }
            float* p0 = C + (size_t)r0 * ldc + cc;
            float* p1 = C + (size_t)r1 * ldc + cc;
            if (ACC) {
                float2 e0 = *(const float2*)p0, e1 = *(const float2*)p1;
                v0.x += e0.x; v0.y += e0.y; v1.x += e1.x; v1.y += e1.y;
            }
            *(float2*)p0 = v0;
            *(float2*)p1 = v1;
        }
    }
}

// ---------------- rmsnorm (+weight) (+rope), one warp per (token, head) ----------------
__global__ void norm_rope_kernel(float* __restrict__ t, const float* __restrict__ w,
                                 const float* __restrict__ cs, const float* __restrict__ sn,
                                 int rows, int do_rope)
{
    int gwarp = (blockIdx.x * blockDim.x + threadIdx.x) >> 5;
    int lane = threadIdx.x & 31;
    if (gwarp >= rows * NHEAD) return;
    int s = gwarp / NHEAD, h = gwarp % NHEAD;
    float* p = t + (size_t)s * D_MODEL + h * HDIM + lane * 4;
    float4 x = *(const float4*)p;
    float ss = x.x * x.x + x.y * x.y + x.z * x.z + x.w * x.w;
#pragma unroll
    for (int off = 16; off >= 1; off >>= 1) ss += __shfl_xor_sync(0xffffffffu, ss, off);
    float inv = rsqrtf(ss * (1.0f / HDIM) + EPSV);
    x.x *= inv; x.y *= inv; x.z *= inv; x.w *= inv;
    if (w) {
        float4 wv = *(const float4*)(w + lane * 4);
        x.x *= wv.x; x.y *= wv.y; x.z *= wv.z; x.w *= wv.w;
    }
    if (do_rope) {
        float4 c = *(const float4*)(cs + (size_t)s * HDIM + lane * 4);
        float4 v = *(const float4*)(sn + (size_t)s * HDIM + lane * 4);
        float o0 = x.x * c.x - x.y * v.x;
        float o1 = x.y * c.y + x.x * v.y;
        float o2 = x.z * c.z - x.w * v.z;
        float o3 = x.w * c.w + x.z * v.w;
        x.x = o0; x.y = o1; x.z = o2; x.w = o3;
    }
    *(float4*)p = x;
}

// ================= flash attention (tf32 tensor) =================
// Bq=128 (8 warps x 16 q-rows), Bk=64, HD=128. Q in register fragments.
// Smem: Ks [128hd][72kv] (transposed), Vs [64kv][136d], Ps [64kv][136q].
__global__ __launch_bounds__(256, 1) void attn_tc(
    const float* __restrict__ Q, const float* __restrict__ Kp,
    const float* __restrict__ Vp, float* __restrict__ Out,
    int kv_len, int masked, int addout)
{
    extern __shared__ unsigned sm_u[];
    unsigned* Ks = sm_u;                  // 128*72
    unsigned* Vs = sm_u + 128 * 72;       // 64*136
    unsigned* Ps = Vs + 64 * 136;         // 64*136

    const int tid = threadIdx.x;
    const int l = tid & 31, w = tid >> 5;
    const int g = l >> 2, t = l & 3;
    const int h = blockIdx.y;
    const int q0 = blockIdx.x << 7;
    const int qr = q0 + w * 16 + g;

    // Q fragments (scaled, tf32)
    unsigned qf[16][4];
    {
        const float* qp  = Q + (size_t)qr * D_MODEL + h * HDIM;
        const float* qp8 = qp + (size_t)8 * D_MODEL;
#pragma unroll
        for (int ks = 0; ks < 16; ks++) {
            const int cb = ks * 8 + t;
            qf[ks][0] = f2tf(qp[cb] * QSCALE);
            qf[ks][1] = f2tf(qp8[cb] * QSCALE);
            qf[ks][2] = f2tf(qp[cb + 4] * QSCALE);
            qf[ks][3] = f2tf(qp8[cb + 4] * QSCALE);
        }
    }

    float o[16][4];
#pragma unroll
    for (int nt = 0; nt < 16; nt++)
#pragma unroll
        for (int i = 0; i < 4; i++) o[nt][i] = 0.f;
    float mrow0 = -1e30f, mrow1 = -1e30f;
    float lrow0 = 0.f, lrow1 = 0.f;

    const int ldr = tid & 63;
    const int ldc0 = (tid >> 6) << 5;

    const int kt0 = (masked && q0 >= BLOCK_TOK) ? BLOCK_TOK : 0;
    for (int kt = kt0; kt < kv_len; kt += 64) {
        __syncthreads();
        {
            const float* kg = Kp + (size_t)(kt + ldr) * D_MODEL + h * HDIM + ldc0;
            const float* vg = Vp + (size_t)(kt + ldr) * D_MODEL + h * HDIM + ldc0;
#pragma unroll
            for (int i = 0; i < 8; i++) {
                float4 kk = *(const float4*)(kg + i * 4);
                Ks[(ldc0 + i * 4 + 0) * 72 + ldr] = f2tf(kk.x);
                Ks[(ldc0 + i * 4 + 1) * 72 + ldr] = f2tf(kk.y);
                Ks[(ldc0 + i * 4 + 2) * 72 + ldr] = f2tf(kk.z);
                Ks[(ldc0 + i * 4 + 3) * 72 + ldr] = f2tf(kk.w);
                float4 vv = *(const float4*)(vg + i * 4);
                uint4 pv;
                pv.x = f2tf(vv.x); pv.y = f2tf(vv.y); pv.z = f2tf(vv.z); pv.w = f2tf(vv.w);
                *(uint4*)&Vs[ldr * 136 + ldc0 + i * 4] = pv;
            }
        }
        __syncthreads();

        // S = Q K^T (log2-scaled)
        float s[8][4];
#pragma unroll
        for (int nt = 0; nt < 8; nt++)
#pragma unroll
            for (int i = 0; i < 4; i++) s[nt][i] = 0.f;
#pragma unroll
        for (int ks = 0; ks < 16; ks++) {
            const int kr = ks * 8 + t;
#pragma unroll
            for (int nt = 0; nt < 8; nt++) {
                unsigned b0 = Ks[kr * 72 + nt * 8 + g];
                unsigned b1 = Ks[(kr + 4) * 72 + nt * 8 + g];
                mma8(s[nt], qf[ks], b0, b1);
            }
        }

        // online softmax
        float mx0 = -1e30f, mx1 = -1e30f;
#pragma unroll
        for (int nt = 0; nt < 8; nt++) {
            mx0 = fmaxf(mx0, fmaxf(s[nt][0], s[nt][1]));
            mx1 = fmaxf(mx1, fmaxf(s[nt][2], s[nt][3]));
        }
        mx0 = fmaxf(mx0, __shfl_xor_sync(0xffffffffu, mx0, 1));
        mx0 = fmaxf(mx0, __shfl_xor_sync(0xffffffffu, mx0, 2));
        mx1 = fmaxf(mx1, __shfl_xor_sync(0xffffffffu, mx1, 1));
        mx1 = fmaxf(mx1, __shfl_xor_sync(0xffffffffu, mx1, 2));
        const float mn0 = fmaxf(mrow0, mx0), mn1 = fmaxf(mrow1, mx1);
        const float al0 = exp2f(mrow0 - mn0), al1 = exp2f(mrow1 - mn1);
        mrow0 = mn0; mrow1 = mn1;

        float sum0 = 0.f, sum1 = 0.f;
#pragma unroll
        for (int nt = 0; nt < 8; nt++) {
            float p0 = exp2f(s[nt][0] - mn0);
            float p1 = exp2f(s[nt][1] - mn0);
            float p2 = exp2f(s[nt][2] - mn1);
            float p3 = exp2f(s[nt][3] - mn1);
            sum0 += p0 + p1;
            sum1 += p2 + p3;
            const int nb = nt * 8 + 2 * t;
            Ps[(nb + 0) * 136 + w * 16 + g]     = f2tf(p0);
            Ps[(nb + 1) * 136 + w * 16 + g]     = f2tf(p1);
            Ps[(nb + 0) * 136 + w * 16 + g + 8] = f2tf(p2);
            Ps[(nb + 1) * 136 + w * 16 + g + 8] = f2tf(p3);
        }
        sum0 += __shfl_xor_sync(0xffffffffu, sum0, 1);
        sum0 += __shfl_xor_sync(0xffffffffu, sum0, 2);
        sum1 += __shfl_xor_sync(0xffffffffu, sum1, 1);
        sum1 += __shfl_xor_sync(0xffffffffu, sum1, 2);
        lrow0 = lrow0 * al0 + sum0;
        lrow1 = lrow1 * al1 + sum1;
#pragma unroll
        for (int nt = 0; nt < 16; nt++) {
            o[nt][0] *= al0; o[nt][1] *= al0;
            o[nt][2] *= al1; o[nt][3] *= al1;
        }
        __syncwarp();

        // O += P V
#pragma unroll
        for (int ks = 0; ks < 8; ks++) {
            const int kr = ks * 8 + t;
            unsigned pa[4];
            pa[0] = Ps[kr * 136 + w * 16 + g];
            pa[1] = Ps[kr * 136 + w * 16 + g + 8];
            pa[2] = Ps[(kr + 4) * 136 + w * 16 + g];
            pa[3] = Ps[(kr + 4) * 136 + w * 16 + g + 8];
#pragma unroll
            for (int nt = 0; nt < 16; nt++) {
                unsigned b0 = Vs[kr * 136 + nt * 8 + g];
                unsigned b1 = Vs[(kr + 4) * 136 + nt * 8 + g];
                mma8(o[nt], pa, b0, b1);
            }
        }
    }

    // epilogue
    const float inv0 = 1.f / lrow0, inv1 = 1.f / lrow1;
    float* op0 = Out + (size_t)qr * D_MODEL + h * HDIM;
    float* op1 = op0 + (size_t)8 * D_MODEL;
#pragma unroll
    for (int nt = 0; nt < 16; nt++) {
        const int cc = nt * 8 + 2 * t;
        float2 v0 = make_float2(o[nt][0] * inv0, o[nt][1] * inv0);
        float2 v1 = make_float2(o[nt][2] * inv1, o[nt][3] * inv1);
        if (addout) {
            float2 e0 = *(const float2*)(op0 + cc);
            float2 e1 = *(const float2*)(op1 + cc);
            v0.x += e0.x; v0.y += e0.y; v1.x += e1.x; v1.y += e1.y;
        }
        *(float2*)(op0 + cc) = v0;
        *(float2*)(op1 + cc) = v1;
    }
}

// ---------------- host launcher ----------------
extern "C" void kernel_launch(void* const* d_in, const int* in_sizes, int n_in,
                              void* d_out, int out_size)
{
    (void)in_sizes; (void)n_in; (void)out_size;
    const float* x    = (const float*)d_in[0];
    const float* img  = (const float*)d_in[1];
    const float* cosr = (const float*)d_in[2];
    const float* sinr = (const float*)d_in[3];
    const float* Wq   = (const float*)d_in[4];
    const float* bq   = (const float*)d_in[5];
    const float* Wk   = (const float*)d_in[6];
    const float* bk   = (const float*)d_in[7];
    const float* Wv   = (const float*)d_in[8];
    const float* bv   = (const float*)d_in[9];
    const float* qd   = (const float*)d_in[10];
    const float* qu   = (const float*)d_in[11];
    const float* kd   = (const float*)d_in[12];
    const float* ku   = (const float*)d_in[13];
    const float* vd   = (const float*)d_in[14];
    const float* vu   = (const float*)d_in[15];
    const float* nqw  = (const float*)d_in[16];
    const float* nkw  = (const float*)d_in[17];
    const float* Wkip = (const float*)d_in[18];
    const float* Wvip = (const float*)d_in[19];
    float* out = (float*)d_out;

    float *q, *k, *v, *kip, *vip, *lt;
    cudaGetSymbolAddress((void**)&q,   g_q);
    cudaGetSymbolAddress((void**)&k,   g_k);
    cudaGetSymbolAddress((void**)&v,   g_v);
    cudaGetSymbolAddress((void**)&kip, g_kip);
    cudaGetSymbolAddress((void**)&vip, g_vip);
    cudaGetSymbolAddress((void**)&lt,  g_lt);

    // QKV projections (batched over z)
    {
        Gemm3 P;
        P.A[0] = x;  P.A[1] = x;  P.A[2] = x;
        P.B[0] = Wq; P.B[1] = Wk; P.B[2] = Wv;
        P.bias[0] = bq; P.bias[1] = bk; P.bias[2] = bv;
        P.C[0] = q;  P.C[1] = k;  P.C[2] = v;
        gemm_tc<false><<<dim3(D_MODEL / 128, S_TOK / 128, 3), 128>>>(P, D_MODEL, D_MODEL, D_MODEL, D_MODEL);
    }
    // LoRA down (cond rows only)
    {
        const float* xc = x + (size_t)BLOCK_TOK * D_MODEL;
        Gemm3 P;
        P.A[0] = xc; P.A[1] = xc; P.A[2] = xc;
        P.B[0] = qd; P.B[1] = kd; P.B[2] = vd;
        P.bias[0] = nullptr; P.bias[1] = nullptr; P.bias[2] = nullptr;
        P.C[0] = lt; P.C[1] = lt + CONDN * RANKN; P.C[2] = lt + 2 * CONDN * RANKN;
        gemm_tc<false><<<dim3(1, CONDN / 128, 3), 128>>>(P, D_MODEL, D_MODEL, D_MODEL, RANKN);
    }
    // LoRA up, accumulate into q/k/v cond rows (alpha/rank * lora_w = 1)
    {
        Gemm3 P;
        P.A[0] = lt; P.A[1] = lt + CONDN * RANKN; P.A[2] = lt + 2 * CONDN * RANKN;
        P.B[0] = qu; P.B[1] = ku; P.B[2] = vu;
        P.bias[0] = nullptr; P.bias[1] = nullptr; P.bias[2] = nullptr;
        P.C[0] = q + (size_t)BLOCK_TOK * D_MODEL;
        P.C[1] = k + (size_t)BLOCK_TOK * D_MODEL;
        P.C[2] = v + (size_t)BLOCK_TOK * D_MODEL;
        gemm_tc<true><<<dim3(D_MODEL / 128, CONDN / 128, 3), 128>>>(P, RANKN, RANKN, RANKN, D_MODEL);
    }
    // RMSNorm + RoPE on q, k
    {
        int nw = S_TOK * NHEAD;
        norm_rope_kernel<<<(nw * 32 + 255) / 256, 256>>>(q, nqw, cosr, sinr, S_TOK, 1);
        norm_rope_kernel<<<(nw * 32 + 255) / 256, 256>>>(k, nkw, cosr, sinr, S_TOK, 1);
    }
    // IP projections
    {
        Gemm3 P;
        P.A[0] = img;  P.A[1] = img;  P.A[2] = img;
        P.B[0] = Wkip; P.B[1] = Wvip; P.B[2] = Wkip;
        P.bias[0] = nullptr; P.bias[1] = nullptr; P.bias[2] = nullptr;
        P.C[0] = kip; P.C[1] = vip; P.C[2] = kip;
        gemm_tc<false><<<dim3(D_MODEL / 128, T_IPN / 128, 2), 128>>>(P, D_IPN, D_IPN, D_IPN, D_MODEL);
    }
    // RMSNorm (no weight, no rope) on k_ip
    {
        int nwip = T_IPN * NHEAD;
        norm_rope_kernel<<<(nwip * 32 + 255) / 256, 256>>>(kip, nullptr, nullptr, nullptr, T_IPN, 0);
    }
    // Attention
    {
        size_t smem = (size_t)(128 * 72 + 64 * 136 + 64 * 136) * 4;  // 106496 B
        cudaFuncSetAttribute(attn_tc, cudaFuncAttributeMaxDynamicSharedMemorySize, (int)smem);
        attn_tc<<<dim3(S_TOK / 128, NHEAD), 256, smem>>>(q, k, v, out, S_TOK, 1, 0);
        attn_tc<<<dim3(S_TOK / 128, NHEAD), 256, smem>>>(q, kip, vip, out, T_IPN, 0, 1);
    }
}